// round 12
// baseline (speedup 1.0000x reference)
#include <cuda_runtime.h>
#include <cuda_fp16.h>
#include <cstddef>
#include <cstdint>

#define N_NODES_MAX 50000
#define N_EDGES_MAX 800000
#define IN_CH 128
#define HID 64

// ---------------- device scratch (no allocation allowed) ----------------
__device__ int    g_deg[N_NODES_MAX];
__device__ int    g_row[N_NODES_MAX + 1];
__device__ float  g_dinv[N_NODES_MAX];
__device__ int    g_col[N_EDGES_MAX];          // src ids grouped by dst
__device__ int    g_slot[N_EDGES_MAX];         // per-edge rank within its dst bucket
__device__ int    g_bsum[256];                 // per-chunk scan sums (<=196 chunks)
__device__ int    g_bar_count;                 // grid barrier arrive counter (stays 0)
__device__ int    g_bar_gen;                   // grid barrier generation (monotonic)
__device__ __half g_P[N_NODES_MAX * 64];       // fp16 projection buffer (both layers)
__device__ float  g_H[N_NODES_MAX * 64];       // fp32 hidden activations

// ---------------- cp.async helpers ----------------
__device__ __forceinline__ void cp_async16(uint32_t smem_addr, const void* gptr) {
    asm volatile("cp.async.cg.shared.global [%0], [%1], 16;\n"
                 :: "r"(smem_addr), "l"(gptr));
}
__device__ __forceinline__ void cp_commit() {
    asm volatile("cp.async.commit_group;\n");
}
template <int N>
__device__ __forceinline__ void cp_wait() {
    asm volatile("cp.async.wait_group %0;\n" :: "n"(N));
}

// ---------------- grid barrier (all nb blocks resident by construction) ----------------
__device__ __forceinline__ void grid_barrier(int nb) {
    __syncthreads();
    __threadfence();   // publish this block's writes before arriving
    if (threadIdx.x == 0) {
        volatile int* genp = &g_bar_gen;
        int gen = *genp;
        if (atomicAdd(&g_bar_count, 1) == nb - 1) {
            g_bar_count = 0;
            __threadfence();
            atomicAdd(&g_bar_gen, 1);
        } else {
            while (*genp == gen) { }
        }
    }
    __syncthreads();
}

// ---------------- phase bodies ----------------
__device__ void phase_zero_deg(int n, int bid, int nb) {
    for (int i = bid * 256 + threadIdx.x; i < n; i += nb * 256) g_deg[i] = 0;
}

// count: 4 edges/iter, atomic WITH return records the edge's slot
__device__ void phase_count(const int* __restrict__ dst, int E, int bid, int nb) {
    int step = nb * 256 * 4;
    for (int i0 = (bid * 256 + threadIdx.x) * 4; i0 < E; i0 += step) {
        if (i0 + 4 <= E) {
            int4 d = *reinterpret_cast<const int4*>(dst + i0);
            int4 sl;
            sl.x = atomicAdd(&g_deg[d.x], 1);
            sl.y = atomicAdd(&g_deg[d.y], 1);
            sl.z = atomicAdd(&g_deg[d.z], 1);
            sl.w = atomicAdd(&g_deg[d.w], 1);
            *reinterpret_cast<int4*>(g_slot + i0) = sl;
        } else {
            for (int j = 0; j < 4 && i0 + j < E; j++)
                g_slot[i0 + j] = atomicAdd(&g_deg[dst[i0 + j]], 1);
        }
    }
}

// 256-thread block inclusive scan
__device__ __forceinline__ int block_scan_256(int v, int* ws) {
    int lane = threadIdx.x & 31;
    int wid = threadIdx.x >> 5;
    int x = v;
    #pragma unroll
    for (int off = 1; off < 32; off <<= 1) {
        int y = __shfl_up_sync(0xFFFFFFFFu, x, off);
        if (lane >= off) x += y;
    }
    if (lane == 31) ws[wid] = x;
    __syncthreads();
    if (wid == 0 && lane < 8) {
        int w = ws[lane];
        #pragma unroll
        for (int off = 1; off < 8; off <<= 1) {
            int y = __shfl_up_sync(0x000000FFu, w, off);
            if (lane >= off) w += y;
        }
        ws[lane] = w;
    }
    __syncthreads();
    return x + ((wid > 0) ? ws[wid - 1] : 0);
}

__device__ void phase_scan_local(int n, int bid, int nb, int* ws) {
    int nchunk = (n + 255) >> 8;
    for (int c = bid; c < nchunk; c += nb) {
        int i = c * 256 + threadIdx.x;
        int v = (i < n) ? g_deg[i] : 0;
        int incl = block_scan_256(v, ws);
        if (i < n) {
            g_row[i] = incl - v;                  // local exclusive
            g_dinv[i] = rsqrtf((float)v + 1.0f);  // deg incl. self-loop
        }
        if (threadIdx.x == 255) g_bsum[c] = incl; // chunk total
        __syncthreads();
    }
}

__device__ void phase_scan_offsets(int n, int E, int bid, int nb, int* s_off) {
    int nchunk = (n + 255) >> 8;
    for (int c = bid; c < nchunk; c += nb) {
        if (threadIdx.x < 32) {
            int s = 0;
            for (int j = threadIdx.x; j < c; j += 32) s += g_bsum[j];
            #pragma unroll
            for (int o = 16; o; o >>= 1) s += __shfl_down_sync(0xFFFFFFFFu, s, o);
            if (threadIdx.x == 0) *s_off = s;
        }
        __syncthreads();
        int i = c * 256 + threadIdx.x;
        if (i < n) g_row[i] += *s_off;
        __syncthreads();
    }
    if (bid == 0 && threadIdx.x == 0) g_row[n] = E;
}

// scale P rows by dinv: P'[i] = dinv[i] * P[i]
__device__ void phase_scale_P(int n, int bid, int nb) {
    for (int t = bid * 256 + threadIdx.x; t < n * 8; t += nb * 256) {
        int node = t >> 3;
        int l = t & 7;
        float di = g_dinv[node];
        uint4 v = reinterpret_cast<uint4*>(g_P)[(size_t)node * 8 + l];
        __half2* hp = reinterpret_cast<__half2*>(&v);
        #pragma unroll
        for (int j = 0; j < 4; j++) {
            float2 f = __half22float2(hp[j]);
            hp[j] = __floats2half2_rn(f.x * di, f.y * di);
        }
        reinterpret_cast<uint4*>(g_P)[(size_t)node * 8 + l] = v;
    }
}

// fill: NO atomics — p = row[dst] + slot[i]
__device__ void phase_fill(const int* __restrict__ src, const int* __restrict__ dst,
                           int E, int bid, int nb) {
    int step = nb * 256 * 4;
    for (int i0 = (bid * 256 + threadIdx.x) * 4; i0 < E; i0 += step) {
        if (i0 + 4 <= E) {
            int4 d = *reinterpret_cast<const int4*>(dst + i0);
            int4 s = *reinterpret_cast<const int4*>(src + i0);
            int4 sl = *reinterpret_cast<const int4*>(g_slot + i0);
            g_col[g_row[d.x] + sl.x] = s.x;
            g_col[g_row[d.y] + sl.y] = s.y;
            g_col[g_row[d.z] + sl.z] = s.z;
            g_col[g_row[d.w] + sl.w] = s.w;
        } else {
            for (int j = 0; j < 4 && i0 + j < E; j++)
                g_col[g_row[dst[i0 + j]] + g_slot[i0 + j]] = src[i0 + j];
        }
    }
}

// ---------------- tf32 tensor-core GEMM (tile loop, cp.async 2-stage) ----------------
__device__ __forceinline__ unsigned cvt_tf32(unsigned bits) {
    unsigned r;
    asm("cvt.rna.tf32.f32 %0, %1;" : "=r"(r) : "f"(__uint_as_float(bits)));
    return r;
}
__device__ __forceinline__ void mma_tf32(float* c, unsigned a0, unsigned a1,
                                         unsigned a2, unsigned a3,
                                         unsigned b0, unsigned b1) {
    asm volatile(
        "mma.sync.aligned.m16n8k8.row.col.f32.tf32.tf32.f32 "
        "{%0,%1,%2,%3}, {%4,%5,%6,%7}, {%8,%9}, {%0,%1,%2,%3};"
        : "+f"(c[0]), "+f"(c[1]), "+f"(c[2]), "+f"(c[3])
        : "r"(a0), "r"(a1), "r"(a2), "r"(a3), "r"(b0), "r"(b1));
}

#define XS_STRIDE 40
#define WS_STRIDE 72
#define XS_WORDS (2 * 128 * XS_STRIDE)
#define SMEM_GEMM_BYTES ((XS_WORDS + 2 * 32 * WS_STRIDE) * 4)

template <int K, bool SCALE_DINV>
__device__ void gemm_tiles(const float* __restrict__ X, const float* __restrict__ W,
                           __half* __restrict__ Y, int n, int bid, int nb,
                           unsigned* smem_dyn) {
    const int KC = 32;
    const int NC = K / KC;
    unsigned* Xs = smem_dyn;
    unsigned* Ws = smem_dyn + XS_WORDS;

    int t = threadIdx.x;
    int lane = t & 31;
    int warp = t >> 5;
    int m_w = warp * 16;
    int g = lane >> 2;
    int tig = lane & 3;

    int ntiles = (n + 127) / 128;
    for (int tile = bid; tile < ntiles; tile += nb) {
        int row0 = tile * 128;

        int xr[4], xq[4];
        const float* xsrc[4];
        #pragma unroll
        for (int u = 0; u < 4; u++) {
            int idx = t + u * 256;
            xr[u] = idx >> 3;
            xq[u] = idx & 7;
            int row = row0 + xr[u];
            if (row >= n) row = n - 1;
            xsrc[u] = X + (size_t)row * K + xq[u] * 4;
        }
        int wk[2], wq[2];
        #pragma unroll
        for (int u = 0; u < 2; u++) {
            int idx = t + u * 256;
            wk[u] = idx >> 4;
            wq[u] = idx & 15;
        }

        auto load_chunk = [&](int st, int kc) {
            #pragma unroll
            for (int u = 0; u < 4; u++)
                cp_async16((uint32_t)__cvta_generic_to_shared(
                               &Xs[st * 128 * XS_STRIDE + xr[u] * XS_STRIDE + xq[u] * 4]),
                           xsrc[u] + kc);
            #pragma unroll
            for (int u = 0; u < 2; u++)
                cp_async16((uint32_t)__cvta_generic_to_shared(
                               &Ws[st * 32 * WS_STRIDE + wk[u] * WS_STRIDE + wq[u] * 4]),
                           W + (size_t)(kc + wk[u]) * 64 + wq[u] * 4);
            cp_commit();
        };

        float c[8][4];
        #pragma unroll
        for (int j = 0; j < 8; j++)
            #pragma unroll
            for (int q = 0; q < 4; q++) c[j][q] = 0.0f;

        load_chunk(0, 0);

        #pragma unroll
        for (int cidx = 0; cidx < NC; cidx++) {
            int buf = cidx & 1;
            if (cidx + 1 < NC) {
                load_chunk(buf ^ 1, (cidx + 1) * KC);
                cp_wait<1>();
            } else {
                cp_wait<0>();
            }
            __syncthreads();

            const unsigned* Xb = Xs + buf * 128 * XS_STRIDE;
            const unsigned* Wb = Ws + buf * 32 * WS_STRIDE;
            #pragma unroll
            for (int s = 0; s < KC / 8; s++) {
                int k0 = s * 8;
                unsigned a0 = cvt_tf32(Xb[(m_w + g) * XS_STRIDE + k0 + tig]);
                unsigned a1 = cvt_tf32(Xb[(m_w + g + 8) * XS_STRIDE + k0 + tig]);
                unsigned a2 = cvt_tf32(Xb[(m_w + g) * XS_STRIDE + k0 + tig + 4]);
                unsigned a3 = cvt_tf32(Xb[(m_w + g + 8) * XS_STRIDE + k0 + tig + 4]);
                #pragma unroll
                for (int j = 0; j < 8; j++) {
                    unsigned b0 = cvt_tf32(Wb[(k0 + tig) * WS_STRIDE + j * 8 + g]);
                    unsigned b1 = cvt_tf32(Wb[(k0 + tig + 4) * WS_STRIDE + j * 8 + g]);
                    mma_tf32(c[j], a0, a1, a2, a3, b0, b1);
                }
            }
            __syncthreads();
        }

        int r0 = row0 + m_w + g;
        int r1 = r0 + 8;
        float s0 = 1.0f, s1 = 1.0f;
        if (SCALE_DINV) {
            s0 = (r0 < n) ? g_dinv[r0] : 0.0f;
            s1 = (r1 < n) ? g_dinv[r1] : 0.0f;
        }
        #pragma unroll
        for (int j = 0; j < 8; j++) {
            int colb = j * 8 + 2 * tig;
            if (r0 < n)
                *reinterpret_cast<__half2*>(Y + (size_t)r0 * 64 + colb) =
                    __floats2half2_rn(c[j][0] * s0, c[j][1] * s0);
            if (r1 < n)
                *reinterpret_cast<__half2*>(Y + (size_t)r1 * 64 + colb) =
                    __floats2half2_rn(c[j][2] * s1, c[j][3] * s1);
        }
    }
}

// ---------------- aggregation on pre-scaled P': out = dinv[d]*(ΣP'[src] + P'[d]) + b ----------------
template <bool RELU>
__device__ void spmm_nodes(const __half* __restrict__ P, const float* __restrict__ bias,
                           float* __restrict__ Y, int n, int bid, int nb) {
    const uint4* Pv = reinterpret_cast<const uint4*>(P);
    int total = n * 8;
    for (int t = bid * 256 + threadIdx.x; t < total; t += nb * 256) {
        int node = t >> 3;
        int l = t & 7;
        float di = g_dinv[node];

        float acc[8];
        {
            uint4 v = Pv[(size_t)node * 8 + l];   // self-loop term P'[node]
            const __half2* hp = reinterpret_cast<const __half2*>(&v);
            #pragma unroll
            for (int j = 0; j < 4; j++) {
                float2 f = __half22float2(hp[j]);
                acc[2 * j]     = f.x;
                acc[2 * j + 1] = f.y;
            }
        }

        int e = g_row[node];
        int end = g_row[node + 1];
        for (; e + 4 <= end; e += 4) {
            int s0 = g_col[e], s1 = g_col[e + 1], s2 = g_col[e + 2], s3 = g_col[e + 3];
            uint4 v0 = Pv[(size_t)s0 * 8 + l];
            uint4 v1 = Pv[(size_t)s1 * 8 + l];
            uint4 v2 = Pv[(size_t)s2 * 8 + l];
            uint4 v3 = Pv[(size_t)s3 * 8 + l];
            const __half2* h0 = reinterpret_cast<const __half2*>(&v0);
            const __half2* h1 = reinterpret_cast<const __half2*>(&v1);
            const __half2* h2 = reinterpret_cast<const __half2*>(&v2);
            const __half2* h3 = reinterpret_cast<const __half2*>(&v3);
            #pragma unroll
            for (int j = 0; j < 4; j++) {
                float2 f0 = __half22float2(h0[j]);
                float2 f1 = __half22float2(h1[j]);
                float2 f2 = __half22float2(h2[j]);
                float2 f3 = __half22float2(h3[j]);
                acc[2 * j]     += (f0.x + f1.x) + (f2.x + f3.x);
                acc[2 * j + 1] += (f0.y + f1.y) + (f2.y + f3.y);
            }
        }
        for (; e < end; e++) {
            int s0 = g_col[e];
            uint4 v0 = Pv[(size_t)s0 * 8 + l];
            const __half2* h0 = reinterpret_cast<const __half2*>(&v0);
            #pragma unroll
            for (int j = 0; j < 4; j++) {
                float2 f0 = __half22float2(h0[j]);
                acc[2 * j]     += f0.x;
                acc[2 * j + 1] += f0.y;
            }
        }

        float4 b0 = reinterpret_cast<const float4*>(bias)[l * 2];
        float4 b1 = reinterpret_cast<const float4*>(bias)[l * 2 + 1];
        acc[0] = acc[0] * di + b0.x; acc[1] = acc[1] * di + b0.y;
        acc[2] = acc[2] * di + b0.z; acc[3] = acc[3] * di + b0.w;
        acc[4] = acc[4] * di + b1.x; acc[5] = acc[5] * di + b1.y;
        acc[6] = acc[6] * di + b1.z; acc[7] = acc[7] * di + b1.w;
        if (RELU) {
            #pragma unroll
            for (int j = 0; j < 8; j++) acc[j] = fmaxf(acc[j], 0.0f);
        }
        float4* Yo = reinterpret_cast<float4*>(Y + (size_t)node * 64 + l * 8);
        Yo[0] = make_float4(acc[0], acc[1], acc[2], acc[3]);
        Yo[1] = make_float4(acc[4], acc[5], acc[6], acc[7]);
    }
}

// ---------------- the megakernel ----------------
__global__ void __launch_bounds__(256, 2) mega_kernel(
    const float* __restrict__ x, const int* __restrict__ src, const int* __restrict__ dst,
    const float* __restrict__ W1, const float* __restrict__ b1,
    const float* __restrict__ W2, const float* __restrict__ b2,
    float* __restrict__ out, int n, int E, int nb)
{
    extern __shared__ unsigned smem_dyn[];
    __shared__ int ws[8];
    __shared__ int s_off;
    int bid = blockIdx.x;

    // P0: zero degree counters
    phase_zero_deg(n, bid, nb);
    grid_barrier(nb);

    // P1: edge count (+slot record), then layer-1 projection tiles (independent)
    phase_count(dst, E, bid, nb);
    gemm_tiles<IN_CH, false>(x, W1, g_P, n, bid, nb, smem_dyn);
    grid_barrier(nb);

    // P2: local scan of degrees + dinv
    phase_scan_local(n, bid, nb, ws);
    grid_barrier(nb);

    // P3: add chunk offsets (-> g_row), then scale P by dinv
    phase_scan_offsets(n, E, bid, nb, &s_off);
    phase_scale_P(n, bid, nb);
    grid_barrier(nb);

    // P4: fill edge lists (atomic-free)
    phase_fill(src, dst, E, bid, nb);
    grid_barrier(nb);

    // P5: layer-1 aggregation (+b1, relu) -> H
    spmm_nodes<true>(g_P, b1, g_H, n, bid, nb);
    grid_barrier(nb);

    // P6: layer-2 projection (dinv folded into epilogue) -> P
    gemm_tiles<HID, true>(g_H, W2, g_P, n, bid, nb, smem_dyn);
    grid_barrier(nb);

    // P7: layer-2 aggregation (+b2) -> out
    spmm_nodes<false>(g_P, b2, out, n, bid, nb);
}

// ---------------- launcher ----------------
extern "C" void kernel_launch(void* const* d_in, const int* in_sizes, int n_in,
                              void* d_out, int out_size) {
    const float* x  = (const float*)d_in[0];       // [n, 128]
    const int*   ei = (const int*)d_in[1];         // [2, E]
    const float* W1 = (const float*)d_in[2];       // [128, 64]
    const float* b1 = (const float*)d_in[3];       // [64]
    const float* W2 = (const float*)d_in[4];       // [64, 64]
    const float* b2 = (const float*)d_in[5];       // [64]
    float* out = (float*)d_out;                    // [n, 64]

    int n = in_sizes[0] / IN_CH;
    int E = in_sizes[1] / 2;
    const int* src = ei;
    const int* dst = ei + E;

    cudaFuncSetAttribute(mega_kernel,
                         cudaFuncAttributeMaxDynamicSharedMemorySize, SMEM_GEMM_BYTES);

    int dev = 0;
    cudaGetDevice(&dev);
    int sms = 0;
    cudaDeviceGetAttribute(&sms, cudaDevAttrMultiProcessorCount, dev);
    int maxb = 0;
    cudaOccupancyMaxActiveBlocksPerMultiprocessor(&maxb, mega_kernel, 256, SMEM_GEMM_BYTES);
    if (maxb < 1) maxb = 1;
    int nb = sms * maxb;   // all blocks co-resident -> grid barrier is deadlock-free

    mega_kernel<<<nb, 256, SMEM_GEMM_BYTES>>>(x, src, dst, W1, b1, W2, b2, out, n, E, nb);
}

// round 13
// speedup vs baseline: 1.2843x; 1.2843x over previous
#include <cuda_runtime.h>
#include <cuda_fp16.h>
#include <cstddef>
#include <cstdint>

#define N_NODES_MAX 50000
#define N_EDGES_MAX 800000
#define IN_CH 128
#define HID 64
#define SCAN_B 1024

// ---------------- device scratch (no allocation allowed) ----------------
__device__ int    g_deg[N_NODES_MAX];
__device__ int    g_row[N_NODES_MAX + 1];
__device__ float  g_dinv[N_NODES_MAX];
__device__ int    g_col[N_EDGES_MAX];          // src ids grouped by dst
__device__ int    g_slot[N_EDGES_MAX];         // per-edge rank within its dst bucket
__device__ int    g_bsum[(N_NODES_MAX + SCAN_B - 1) / SCAN_B + 1];
__device__ int    g_ready;                     // lookback counter
__device__ __half g_P[N_NODES_MAX * 64];       // fp16 projection buffer (both layers)
__device__ float  g_H[N_NODES_MAX * 64];       // fp32 hidden activations

// ---------------- cp.async helpers ----------------
__device__ __forceinline__ void cp_async16(uint32_t smem_addr, const void* gptr) {
    asm volatile("cp.async.cg.shared.global [%0], [%1], 16;\n"
                 :: "r"(smem_addr), "l"(gptr));
}
__device__ __forceinline__ void cp_commit() {
    asm volatile("cp.async.commit_group;\n");
}
template <int N>
__device__ __forceinline__ void cp_wait() {
    asm volatile("cp.async.wait_group %0;\n" :: "n"(N));
}

// ---------------- CSR build ----------------
// count: 4 edges/thread, atomics WITH return -> also records the edge's slot
__global__ void count_deg_kernel(const int* __restrict__ dst, int n_edges) {
    if (blockIdx.x == 0 && threadIdx.x == 0) g_ready = 0;  // for scan (next launch)
    int i0 = (blockIdx.x * blockDim.x + threadIdx.x) * 4;
    if (i0 + 4 <= n_edges) {
        int4 d = *reinterpret_cast<const int4*>(dst + i0);
        int4 sl;
        sl.x = atomicAdd(&g_deg[d.x], 1);
        sl.y = atomicAdd(&g_deg[d.y], 1);
        sl.z = atomicAdd(&g_deg[d.z], 1);
        sl.w = atomicAdd(&g_deg[d.w], 1);
        *reinterpret_cast<int4*>(g_slot + i0) = sl;
    } else {
        for (int j = 0; j < 4 && i0 + j < n_edges; j++)
            g_slot[i0 + j] = atomicAdd(&g_deg[dst[i0 + j]], 1);
    }
}

__device__ __forceinline__ int block_scan_incl(int v, int* warp_sums) {
    int lane = threadIdx.x & 31;
    int wid = threadIdx.x >> 5;
    int x = v;
    #pragma unroll
    for (int off = 1; off < 32; off <<= 1) {
        int y = __shfl_up_sync(0xFFFFFFFFu, x, off);
        if (lane >= off) x += y;
    }
    if (lane == 31) warp_sums[wid] = x;
    __syncthreads();
    if (wid == 0) {
        int w = warp_sums[lane];
        #pragma unroll
        for (int off = 1; off < 32; off <<= 1) {
            int y = __shfl_up_sync(0xFFFFFFFFu, w, off);
            if (lane >= off) w += y;
        }
        warp_sums[lane] = w;
    }
    __syncthreads();
    return x + ((wid > 0) ? warp_sums[wid - 1] : 0);
}

// Single-pass scan with grid-resident counter wait (49 blocks << 148 SMs).
__global__ void __launch_bounds__(SCAN_B) scan_fused_kernel(int n, int E) {
    __shared__ int warp_sums[32];
    __shared__ int s_off;
    int b = blockIdx.x;
    int i = b * SCAN_B + threadIdx.x;
    int v = (i < n) ? g_deg[i] : 0;
    int incl = block_scan_incl(v, warp_sums);

    if (threadIdx.x == 0) {
        g_bsum[b] = warp_sums[31];
        __threadfence();
        atomicAdd(&g_ready, 1);
        while (atomicAdd(&g_ready, 0) < (int)gridDim.x) {}
        __threadfence();
        int s = 0;
        for (int j = 0; j < b; j++) s += g_bsum[j];
        s_off = s;
    }
    __syncthreads();

    if (i < n) {
        g_row[i] = incl - v + s_off;
        g_dinv[i] = rsqrtf((float)v + 1.0f);  // deg incl. self-loop
    }
    if (b == 0 && threadIdx.x == 0) g_row[n] = E;
}

// fill: NO atomics — p = row[dst] + slot[i]
__global__ void fill_edges_kernel(const int* __restrict__ src,
                                  const int* __restrict__ dst, int n_edges) {
    int i0 = (blockIdx.x * blockDim.x + threadIdx.x) * 4;
    if (i0 + 4 <= n_edges) {
        int4 d = *reinterpret_cast<const int4*>(dst + i0);
        int4 s = *reinterpret_cast<const int4*>(src + i0);
        int4 sl = *reinterpret_cast<const int4*>(g_slot + i0);
        g_col[g_row[d.x] + sl.x] = s.x;
        g_col[g_row[d.y] + sl.y] = s.y;
        g_col[g_row[d.z] + sl.z] = s.z;
        g_col[g_row[d.w] + sl.w] = s.w;
    } else {
        for (int j = 0; j < 4 && i0 + j < n_edges; j++)
            g_col[g_row[dst[i0 + j]] + g_slot[i0 + j]] = src[i0 + j];
    }
}

// scale P rows by dinv: P'[i] = dinv[i] * P[i]
__global__ void scale_P_kernel(__half* __restrict__ P, int n) {
    int t = blockIdx.x * blockDim.x + threadIdx.x;
    int node = t >> 3;
    if (node >= n) return;
    int l = t & 7;
    float di = g_dinv[node];
    uint4 v = reinterpret_cast<uint4*>(P)[(size_t)node * 8 + l];
    __half2* hp = reinterpret_cast<__half2*>(&v);
    #pragma unroll
    for (int j = 0; j < 4; j++) {
        float2 f = __half22float2(hp[j]);
        hp[j] = __floats2half2_rn(f.x * di, f.y * di);
    }
    reinterpret_cast<uint4*>(P)[(size_t)node * 8 + l] = v;
}

// ---------------- tf32 tensor-core GEMM with cp.async double buffering ----------------
__device__ __forceinline__ unsigned cvt_tf32(unsigned bits) {
    unsigned r;
    asm("cvt.rna.tf32.f32 %0, %1;" : "=r"(r) : "f"(__uint_as_float(bits)));
    return r;
}

__device__ __forceinline__ void mma_tf32(float* c, unsigned a0, unsigned a1,
                                         unsigned a2, unsigned a3,
                                         unsigned b0, unsigned b1) {
    asm volatile(
        "mma.sync.aligned.m16n8k8.row.col.f32.tf32.tf32.f32 "
        "{%0,%1,%2,%3}, {%4,%5,%6,%7}, {%8,%9}, {%0,%1,%2,%3};"
        : "+f"(c[0]), "+f"(c[1]), "+f"(c[2]), "+f"(c[3])
        : "r"(a0), "r"(a1), "r"(a2), "r"(a3), "r"(b0), "r"(b1));
}

// Dynamic smem layout: Xs[2][64][40] then Ws[2][32][72]  (38912 B total)
#define XS_STRIDE 40
#define WS_STRIDE 72
#define XS_WORDS (2 * 64 * XS_STRIDE)
#define SMEM_GEMM_BYTES ((XS_WORDS + 2 * 32 * WS_STRIDE) * 4)

// 256 threads (8 warps), tile 64 rows x 64 cols, KC=32, 2-stage cp.async pipeline.
// Warp w: rows [(w&3)*16, +16), cols [(w>>2)*32, +32) as 4 m16n8 accumulators.
// Smaller tile -> 38.9KB smem -> 5 blocks/SM residency, 782-block grid: more
// outstanding loads chip-wide for this latency-bound kernel.
template <int K, bool SCALE_DINV>
__global__ void __launch_bounds__(256) gemm_tc_kernel(const float* __restrict__ X,
                                                      const float* __restrict__ W,
                                                      __half* __restrict__ Y, int n) {
    const int KC = 32;
    const int NC = K / KC;
    extern __shared__ unsigned smem_dyn[];
    unsigned* Xs = smem_dyn;                 // Xs[st][row][k]
    unsigned* Ws = smem_dyn + XS_WORDS;      // Ws[st][k][nn]

    int t = threadIdx.x;
    int lane = t & 31;
    int warp = t >> 5;          // 0..7
    int row0 = blockIdx.x * 64;
    int m_w = (warp & 3) * 16;  // row offset within tile
    int n_w = (warp >> 2) * 32; // col offset within tile
    int g = lane >> 2;          // 0..7
    int tig = lane & 3;         // 0..3

    // per-thread load coordinates
    // X chunk: 64 rows x 32 k = 512 float4 -> 2 per thread
    int xr[2], xq[2];
    const float* xsrc[2];
    #pragma unroll
    for (int u = 0; u < 2; u++) {
        int idx = t + u * 256;
        xr[u] = idx >> 3;        // 0..63
        xq[u] = idx & 7;         // float4 along k
        int row = row0 + xr[u];
        if (row >= n) row = n - 1;
        xsrc[u] = X + (size_t)row * K + xq[u] * 4;
    }
    // W chunk: 32 k x 64 n = 512 float4 -> 2 per thread
    int wk[2], wq[2];
    #pragma unroll
    for (int u = 0; u < 2; u++) {
        int idx = t + u * 256;
        wk[u] = idx >> 4;        // 0..31
        wq[u] = idx & 15;        // float4 along n
    }

    auto load_chunk = [&](int st, int kc) {
        #pragma unroll
        for (int u = 0; u < 2; u++)
            cp_async16((uint32_t)__cvta_generic_to_shared(
                           &Xs[st * 64 * XS_STRIDE + xr[u] * XS_STRIDE + xq[u] * 4]),
                       xsrc[u] + kc);
        #pragma unroll
        for (int u = 0; u < 2; u++)
            cp_async16((uint32_t)__cvta_generic_to_shared(
                           &Ws[st * 32 * WS_STRIDE + wk[u] * WS_STRIDE + wq[u] * 4]),
                       W + (size_t)(kc + wk[u]) * 64 + wq[u] * 4);
        cp_commit();
    };

    float c[4][4];
    #pragma unroll
    for (int j = 0; j < 4; j++)
        #pragma unroll
        for (int q = 0; q < 4; q++) c[j][q] = 0.0f;

    load_chunk(0, 0);

    #pragma unroll
    for (int cidx = 0; cidx < NC; cidx++) {
        int buf = cidx & 1;
        if (cidx + 1 < NC) {
            load_chunk(buf ^ 1, (cidx + 1) * KC);
            cp_wait<1>();
        } else {
            cp_wait<0>();
        }
        __syncthreads();

        const unsigned* Xb = Xs + buf * 64 * XS_STRIDE;
        const unsigned* Wb = Ws + buf * 32 * WS_STRIDE;
        #pragma unroll
        for (int s = 0; s < KC / 8; s++) {
            int k0 = s * 8;
            unsigned a0 = cvt_tf32(Xb[(m_w + g) * XS_STRIDE + k0 + tig]);
            unsigned a1 = cvt_tf32(Xb[(m_w + g + 8) * XS_STRIDE + k0 + tig]);
            unsigned a2 = cvt_tf32(Xb[(m_w + g) * XS_STRIDE + k0 + tig + 4]);
            unsigned a3 = cvt_tf32(Xb[(m_w + g + 8) * XS_STRIDE + k0 + tig + 4]);
            #pragma unroll
            for (int j = 0; j < 4; j++) {
                int col = n_w + j * 8 + g;
                unsigned b0 = cvt_tf32(Wb[(k0 + tig) * WS_STRIDE + col]);
                unsigned b1 = cvt_tf32(Wb[(k0 + tig + 4) * WS_STRIDE + col]);
                mma_tf32(c[j], a0, a1, a2, a3, b0, b1);
            }
        }
        __syncthreads();
    }

    // epilogue
    int r0 = row0 + m_w + g;
    int r1 = r0 + 8;
    float s0 = 1.0f, s1 = 1.0f;
    if (SCALE_DINV) {
        s0 = (r0 < n) ? g_dinv[r0] : 0.0f;
        s1 = (r1 < n) ? g_dinv[r1] : 0.0f;
    }
    #pragma unroll
    for (int j = 0; j < 4; j++) {
        int colb = n_w + j * 8 + 2 * tig;
        if (r0 < n)
            *reinterpret_cast<__half2*>(Y + (size_t)r0 * 64 + colb) =
                __floats2half2_rn(c[j][0] * s0, c[j][1] * s0);
        if (r1 < n)
            *reinterpret_cast<__half2*>(Y + (size_t)r1 * 64 + colb) =
                __floats2half2_rn(c[j][2] * s1, c[j][3] * s1);
    }
}

// ---------------- aggregation on pre-scaled P': out = dinv[d]*(ΣP'[src] + P'[d]) + b ----------------
template <bool RELU>
__global__ void __launch_bounds__(256) spmm64_kernel(const __half* __restrict__ P,
                                                     const float* __restrict__ bias,
                                                     float* __restrict__ Y, int n) {
    int t = blockIdx.x * blockDim.x + threadIdx.x;
    int node = t >> 3;
    if (node >= n) return;
    int l = t & 7;

    const uint4* Pv = reinterpret_cast<const uint4*>(P);
    float di = g_dinv[node];

    float acc[8];
    {
        uint4 v = Pv[(size_t)node * 8 + l];   // self-loop term P'[node]
        const __half2* hp = reinterpret_cast<const __half2*>(&v);
        #pragma unroll
        for (int j = 0; j < 4; j++) {
            float2 f = __half22float2(hp[j]);
            acc[2 * j]     = f.x;
            acc[2 * j + 1] = f.y;
        }
    }

    int e = g_row[node];
    int end = g_row[node + 1];
    for (; e + 4 <= end; e += 4) {
        int s0 = g_col[e], s1 = g_col[e + 1], s2 = g_col[e + 2], s3 = g_col[e + 3];
        uint4 v0 = Pv[(size_t)s0 * 8 + l];
        uint4 v1 = Pv[(size_t)s1 * 8 + l];
        uint4 v2 = Pv[(size_t)s2 * 8 + l];
        uint4 v3 = Pv[(size_t)s3 * 8 + l];
        const __half2* h0 = reinterpret_cast<const __half2*>(&v0);
        const __half2* h1 = reinterpret_cast<const __half2*>(&v1);
        const __half2* h2 = reinterpret_cast<const __half2*>(&v2);
        const __half2* h3 = reinterpret_cast<const __half2*>(&v3);
        #pragma unroll
        for (int j = 0; j < 4; j++) {
            float2 f0 = __half22float2(h0[j]);
            float2 f1 = __half22float2(h1[j]);
            float2 f2 = __half22float2(h2[j]);
            float2 f3 = __half22float2(h3[j]);
            acc[2 * j]     += (f0.x + f1.x) + (f2.x + f3.x);
            acc[2 * j + 1] += (f0.y + f1.y) + (f2.y + f3.y);
        }
    }
    for (; e < end; e++) {
        int s0 = g_col[e];
        uint4 v0 = Pv[(size_t)s0 * 8 + l];
        const __half2* h0 = reinterpret_cast<const __half2*>(&v0);
        #pragma unroll
        for (int j = 0; j < 4; j++) {
            float2 f0 = __half22float2(h0[j]);
            acc[2 * j]     += f0.x;
            acc[2 * j + 1] += f0.y;
        }
    }

    float4 b0 = reinterpret_cast<const float4*>(bias)[l * 2];
    float4 b1 = reinterpret_cast<const float4*>(bias)[l * 2 + 1];
    acc[0] = acc[0] * di + b0.x; acc[1] = acc[1] * di + b0.y;
    acc[2] = acc[2] * di + b0.z; acc[3] = acc[3] * di + b0.w;
    acc[4] = acc[4] * di + b1.x; acc[5] = acc[5] * di + b1.y;
    acc[6] = acc[6] * di + b1.z; acc[7] = acc[7] * di + b1.w;
    if (RELU) {
        #pragma unroll
        for (int j = 0; j < 8; j++) acc[j] = fmaxf(acc[j], 0.0f);
    }
    float4* Yo = reinterpret_cast<float4*>(Y + (size_t)node * 64 + l * 8);
    Yo[0] = make_float4(acc[0], acc[1], acc[2], acc[3]);
    Yo[1] = make_float4(acc[4], acc[5], acc[6], acc[7]);
}

// ---------------- launcher ----------------
extern "C" void kernel_launch(void* const* d_in, const int* in_sizes, int n_in,
                              void* d_out, int out_size) {
    const float* x  = (const float*)d_in[0];       // [n, 128]
    const int*   ei = (const int*)d_in[1];         // [2, E]
    const float* W1 = (const float*)d_in[2];       // [128, 64]
    const float* b1 = (const float*)d_in[3];       // [64]
    const float* W2 = (const float*)d_in[4];       // [64, 64]
    const float* b2 = (const float*)d_in[5];       // [64]
    float* out = (float*)d_out;                    // [n, 64]

    int n = in_sizes[0] / IN_CH;
    int E = in_sizes[1] / 2;
    const int* src = ei;
    const int* dst = ei + E;

    void* p;
    cudaGetSymbolAddress(&p, g_P);
    __half* P = (__half*)p;
    cudaGetSymbolAddress(&p, g_H);
    float* H = (float*)p;
    void* deg_ptr;
    cudaGetSymbolAddress(&deg_ptr, g_deg);

    cudaFuncSetAttribute(gemm_tc_kernel<IN_CH, false>,
                         cudaFuncAttributeMaxDynamicSharedMemorySize, SMEM_GEMM_BYTES);
    cudaFuncSetAttribute(gemm_tc_kernel<HID, true>,
                         cudaFuncAttributeMaxDynamicSharedMemorySize, SMEM_GEMM_BYTES);

    int nb = (n + SCAN_B - 1) / SCAN_B;
    int eb4 = (E + 4 * 256 - 1) / (4 * 256);
    int spmm_blocks = (n * 8 + 255) / 256;
    int gemm_blocks = (n + 63) / 64;

    // Fork side stream: CSR build overlaps GEMM1. (Host objects leak by design;
    // destroying capture-participating streams/events mid-capture is illegal.)
    cudaStream_t s2;
    cudaStreamCreateWithFlags(&s2, cudaStreamNonBlocking);
    cudaEvent_t ev_fork, ev_scan, ev_join;
    cudaEventCreateWithFlags(&ev_fork, cudaEventDisableTiming);
    cudaEventCreateWithFlags(&ev_scan, cudaEventDisableTiming);
    cudaEventCreateWithFlags(&ev_join, cudaEventDisableTiming);

    cudaEventRecord(ev_fork, 0);
    cudaStreamWaitEvent(s2, ev_fork, 0);

    // side stream: memset deg -> count(+slot, resets ready) -> scan -> fill (no atomics)
    cudaMemsetAsync(deg_ptr, 0, (size_t)n * sizeof(int), s2);
    count_deg_kernel<<<eb4, 256, 0, s2>>>(dst, E);
    scan_fused_kernel<<<nb, SCAN_B, 0, s2>>>(n, E);
    cudaEventRecord(ev_scan, s2);
    fill_edges_kernel<<<eb4, 256, 0, s2>>>(src, dst, E);
    cudaEventRecord(ev_join, s2);

    // main stream: layer-1 projection (tensor cores), concurrent with CSR build
    gemm_tc_kernel<IN_CH, false><<<gemm_blocks, 256, SMEM_GEMM_BYTES>>>(x, W1, P, n);

    // scale P by dinv (needs scan only) — overlaps fill_edges
    cudaStreamWaitEvent(0, ev_scan, 0);
    scale_P_kernel<<<(n * 8 + 255) / 256, 256>>>(P, n);

    // aggregate layer 1 (needs fill)
    cudaStreamWaitEvent(0, ev_join, 0);
    spmm64_kernel<true><<<spmm_blocks, 256>>>(P, b1, H, n);

    // layer 2: project with dinv folded into epilogue, aggregate
    gemm_tc_kernel<HID, true><<<gemm_blocks, 256, SMEM_GEMM_BYTES>>>(H, W2, P, n);
    spmm64_kernel<false><<<spmm_blocks, 256>>>(P, b2, out, n);
}

// round 14
// speedup vs baseline: 1.3815x; 1.0757x over previous
#include <cuda_runtime.h>
#include <cuda_fp16.h>
#include <cstddef>
#include <cstdint>

#define N_NODES_MAX 50000
#define N_EDGES_MAX 800000
#define IN_CH 128
#define HID 64
#define SCAN_B 1024

// ---------------- device scratch (no allocation allowed) ----------------
__device__ int    g_deg[N_NODES_MAX];          // zero-init at load; re-zeroed by scan each run
__device__ int    g_row[N_NODES_MAX + 1];
__device__ float  g_dinv[N_NODES_MAX];
__device__ int    g_col[N_EDGES_MAX];          // src ids grouped by dst
__device__ int    g_slot[N_EDGES_MAX];         // per-edge rank within its dst bucket
__device__ int    g_bsum[(N_NODES_MAX + SCAN_B - 1) / SCAN_B + 1];
__device__ int    g_ready;                     // lookback counter
__device__ __half g_P[N_NODES_MAX * 64];       // fp16 projection buffer (both layers)
__device__ float  g_H[N_NODES_MAX * 64];       // fp32 hidden activations

// ---------------- cp.async helpers ----------------
__device__ __forceinline__ void cp_async16(uint32_t smem_addr, const void* gptr) {
    asm volatile("cp.async.cg.shared.global [%0], [%1], 16;\n"
                 :: "r"(smem_addr), "l"(gptr));
}
__device__ __forceinline__ void cp_commit() {
    asm volatile("cp.async.commit_group;\n");
}
template <int N>
__device__ __forceinline__ void cp_wait() {
    asm volatile("cp.async.wait_group %0;\n" :: "n"(N));
}

// ---------------- CSR build ----------------
// count: 2 edges/thread (max resident warps; ATOMG latency-bound), slot = atomic return
__global__ void count_deg_kernel(const int* __restrict__ dst, int n_edges) {
    if (blockIdx.x == 0 && threadIdx.x == 0) g_ready = 0;  // for scan (next launch)
    int i0 = (blockIdx.x * blockDim.x + threadIdx.x) * 2;
    if (i0 + 2 <= n_edges) {
        int2 d = *reinterpret_cast<const int2*>(dst + i0);
        int2 sl;
        sl.x = atomicAdd(&g_deg[d.x], 1);
        sl.y = atomicAdd(&g_deg[d.y], 1);
        *reinterpret_cast<int2*>(g_slot + i0) = sl;
    } else if (i0 < n_edges) {
        g_slot[i0] = atomicAdd(&g_deg[dst[i0]], 1);
    }
}

__device__ __forceinline__ int block_scan_incl(int v, int* warp_sums) {
    int lane = threadIdx.x & 31;
    int wid = threadIdx.x >> 5;
    int x = v;
    #pragma unroll
    for (int off = 1; off < 32; off <<= 1) {
        int y = __shfl_up_sync(0xFFFFFFFFu, x, off);
        if (lane >= off) x += y;
    }
    if (lane == 31) warp_sums[wid] = x;
    __syncthreads();
    if (wid == 0) {
        int w = warp_sums[lane];
        #pragma unroll
        for (int off = 1; off < 32; off <<= 1) {
            int y = __shfl_up_sync(0xFFFFFFFFu, w, off);
            if (lane >= off) w += y;
        }
        warp_sums[lane] = w;
    }
    __syncthreads();
    return x + ((wid > 0) ? warp_sums[wid - 1] : 0);
}

// Single-pass scan with grid-resident counter wait (49 blocks << 148 SMs).
// Also RE-ZEROES g_deg so the next kernel_launch starts clean (replaces memset).
__global__ void __launch_bounds__(SCAN_B) scan_fused_kernel(int n, int E) {
    __shared__ int warp_sums[32];
    __shared__ int s_off;
    int b = blockIdx.x;
    int i = b * SCAN_B + threadIdx.x;
    int v = (i < n) ? g_deg[i] : 0;
    int incl = block_scan_incl(v, warp_sums);

    if (threadIdx.x == 0) {
        g_bsum[b] = warp_sums[31];
        __threadfence();
        atomicAdd(&g_ready, 1);
        while (atomicAdd(&g_ready, 0) < (int)gridDim.x) {}
        __threadfence();
        int s = 0;
        for (int j = 0; j < b; j++) s += g_bsum[j];
        s_off = s;
    }
    __syncthreads();

    if (i < n) {
        g_row[i] = incl - v + s_off;
        g_dinv[i] = rsqrtf((float)v + 1.0f);  // deg incl. self-loop
        g_deg[i] = 0;                          // ready for next launch
    }
    if (b == 0 && threadIdx.x == 0) g_row[n] = E;
}

// fill: NO atomics — p = row[dst] + slot[i]; 2 edges/thread
__global__ void fill_edges_kernel(const int* __restrict__ src,
                                  const int* __restrict__ dst, int n_edges) {
    int i0 = (blockIdx.x * blockDim.x + threadIdx.x) * 2;
    if (i0 + 2 <= n_edges) {
        int2 d = *reinterpret_cast<const int2*>(dst + i0);
        int2 s = *reinterpret_cast<const int2*>(src + i0);
        int2 sl = *reinterpret_cast<const int2*>(g_slot + i0);
        g_col[g_row[d.x] + sl.x] = s.x;
        g_col[g_row[d.y] + sl.y] = s.y;
    } else if (i0 < n_edges) {
        g_col[g_row[dst[i0]] + g_slot[i0]] = src[i0];
    }
}

// scale P rows by dinv: P'[i] = dinv[i] * P[i]
__global__ void scale_P_kernel(__half* __restrict__ P, int n) {
    int t = blockIdx.x * blockDim.x + threadIdx.x;
    int node = t >> 3;
    if (node >= n) return;
    int l = t & 7;
    float di = g_dinv[node];
    uint4 v = reinterpret_cast<uint4*>(P)[(size_t)node * 8 + l];
    __half2* hp = reinterpret_cast<__half2*>(&v);
    #pragma unroll
    for (int j = 0; j < 4; j++) {
        float2 f = __half22float2(hp[j]);
        hp[j] = __floats2half2_rn(f.x * di, f.y * di);
    }
    reinterpret_cast<uint4*>(P)[(size_t)node * 8 + l] = v;
}

// ---------------- tf32 tensor-core GEMM with cp.async double buffering ----------------
__device__ __forceinline__ unsigned cvt_tf32(unsigned bits) {
    unsigned r;
    asm("cvt.rna.tf32.f32 %0, %1;" : "=r"(r) : "f"(__uint_as_float(bits)));
    return r;
}

__device__ __forceinline__ void mma_tf32(float* c, unsigned a0, unsigned a1,
                                         unsigned a2, unsigned a3,
                                         unsigned b0, unsigned b1) {
    asm volatile(
        "mma.sync.aligned.m16n8k8.row.col.f32.tf32.tf32.f32 "
        "{%0,%1,%2,%3}, {%4,%5,%6,%7}, {%8,%9}, {%0,%1,%2,%3};"
        : "+f"(c[0]), "+f"(c[1]), "+f"(c[2]), "+f"(c[3])
        : "r"(a0), "r"(a1), "r"(a2), "r"(a3), "r"(b0), "r"(b1));
}

// Dynamic smem layout: Xs[2][128][40] then Ws[2][32][72]  (59392 B total)
#define XS_STRIDE 40
#define WS_STRIDE 72
#define XS_WORDS (2 * 128 * XS_STRIDE)
#define SMEM_GEMM_BYTES ((XS_WORDS + 2 * 32 * WS_STRIDE) * 4)

// 256 threads (8 warps), tile 128 rows x 64 cols, KC=32, 2-stage cp.async pipeline.
// fp32 bits staged via cp.async; cvt.rna.tf32 on register fragments.
// Xs stride 40 (==8 mod 32) and Ws stride 72 (==8 mod 32): conflict-free frag loads.
template <int K, bool SCALE_DINV>
__global__ void __launch_bounds__(256) gemm_tc_kernel(const float* __restrict__ X,
                                                      const float* __restrict__ W,
                                                      __half* __restrict__ Y, int n) {
    const int KC = 32;
    const int NC = K / KC;
    extern __shared__ unsigned smem_dyn[];
    unsigned* Xs = smem_dyn;                 // Xs[st][row][k]
    unsigned* Ws = smem_dyn + XS_WORDS;      // Ws[st][k][nn]

    int t = threadIdx.x;
    int lane = t & 31;
    int warp = t >> 5;          // 0..7
    int row0 = blockIdx.x * 128;
    int m_w = warp * 16;
    int g = lane >> 2;          // 0..7
    int tig = lane & 3;         // 0..3

    int xr[4], xq[4];
    const float* xsrc[4];
    #pragma unroll
    for (int u = 0; u < 4; u++) {
        int idx = t + u * 256;
        xr[u] = idx >> 3;        // 0..127
        xq[u] = idx & 7;         // float4 along k
        int row = row0 + xr[u];
        if (row >= n) row = n - 1;
        xsrc[u] = X + (size_t)row * K + xq[u] * 4;
    }
    int wk[2], wq[2];
    #pragma unroll
    for (int u = 0; u < 2; u++) {
        int idx = t + u * 256;
        wk[u] = idx >> 4;        // 0..31
        wq[u] = idx & 15;        // float4 along n
    }

    auto load_chunk = [&](int st, int kc) {
        #pragma unroll
        for (int u = 0; u < 4; u++)
            cp_async16((uint32_t)__cvta_generic_to_shared(
                           &Xs[st * 128 * XS_STRIDE + xr[u] * XS_STRIDE + xq[u] * 4]),
                       xsrc[u] + kc);
        #pragma unroll
        for (int u = 0; u < 2; u++)
            cp_async16((uint32_t)__cvta_generic_to_shared(
                           &Ws[st * 32 * WS_STRIDE + wk[u] * WS_STRIDE + wq[u] * 4]),
                       W + (size_t)(kc + wk[u]) * 64 + wq[u] * 4);
        cp_commit();
    };

    float c[8][4];
    #pragma unroll
    for (int j = 0; j < 8; j++)
        #pragma unroll
        for (int q = 0; q < 4; q++) c[j][q] = 0.0f;

    load_chunk(0, 0);

    #pragma unroll
    for (int cidx = 0; cidx < NC; cidx++) {
        int buf = cidx & 1;
        if (cidx + 1 < NC) {
            load_chunk(buf ^ 1, (cidx + 1) * KC);
            cp_wait<1>();
        } else {
            cp_wait<0>();
        }
        __syncthreads();

        const unsigned* Xb = Xs + buf * 128 * XS_STRIDE;
        const unsigned* Wb = Ws + buf * 32 * WS_STRIDE;
        #pragma unroll
        for (int s = 0; s < KC / 8; s++) {
            int k0 = s * 8;
            unsigned a0 = cvt_tf32(Xb[(m_w + g) * XS_STRIDE + k0 + tig]);
            unsigned a1 = cvt_tf32(Xb[(m_w + g + 8) * XS_STRIDE + k0 + tig]);
            unsigned a2 = cvt_tf32(Xb[(m_w + g) * XS_STRIDE + k0 + tig + 4]);
            unsigned a3 = cvt_tf32(Xb[(m_w + g + 8) * XS_STRIDE + k0 + tig + 4]);
            #pragma unroll
            for (int j = 0; j < 8; j++) {
                unsigned b0 = cvt_tf32(Wb[(k0 + tig) * WS_STRIDE + j * 8 + g]);
                unsigned b1 = cvt_tf32(Wb[(k0 + tig + 4) * WS_STRIDE + j * 8 + g]);
                mma_tf32(c[j], a0, a1, a2, a3, b0, b1);
            }
        }
        __syncthreads();
    }

    // epilogue
    int r0 = row0 + m_w + g;
    int r1 = r0 + 8;
    float s0 = 1.0f, s1 = 1.0f;
    if (SCALE_DINV) {
        s0 = (r0 < n) ? g_dinv[r0] : 0.0f;
        s1 = (r1 < n) ? g_dinv[r1] : 0.0f;
    }
    #pragma unroll
    for (int j = 0; j < 8; j++) {
        int colb = j * 8 + 2 * tig;
        if (r0 < n)
            *reinterpret_cast<__half2*>(Y + (size_t)r0 * 64 + colb) =
                __floats2half2_rn(c[j][0] * s0, c[j][1] * s0);
        if (r1 < n)
            *reinterpret_cast<__half2*>(Y + (size_t)r1 * 64 + colb) =
                __floats2half2_rn(c[j][2] * s1, c[j][3] * s1);
    }
}

// ---------------- aggregation on pre-scaled P': out = dinv[d]*(ΣP'[src] + P'[d]) + b ----------------
template <bool RELU>
__global__ void __launch_bounds__(256) spmm64_kernel(const __half* __restrict__ P,
                                                     const float* __restrict__ bias,
                                                     float* __restrict__ Y, int n) {
    int t = blockIdx.x * blockDim.x + threadIdx.x;
    int node = t >> 3;
    if (node >= n) return;
    int l = t & 7;

    const uint4* Pv = reinterpret_cast<const uint4*>(P);
    float di = g_dinv[node];

    float acc[8];
    {
        uint4 v = Pv[(size_t)node * 8 + l];   // self-loop term P'[node]
        const __half2* hp = reinterpret_cast<const __half2*>(&v);
        #pragma unroll
        for (int j = 0; j < 4; j++) {
            float2 f = __half22float2(hp[j]);
            acc[2 * j]     = f.x;
            acc[2 * j + 1] = f.y;
        }
    }

    int e = g_row[node];
    int end = g_row[node + 1];
    // 8-way unrolled gathers: 8 independent 128B-line loads in flight
    for (; e + 8 <= end; e += 8) {
        int sidx[8];
        #pragma unroll
        for (int u = 0; u < 8; u++) sidx[u] = g_col[e + u];
        uint4 v[8];
        #pragma unroll
        for (int u = 0; u < 8; u++) v[u] = Pv[(size_t)sidx[u] * 8 + l];
        #pragma unroll
        for (int u = 0; u < 8; u++) {
            const __half2* hp = reinterpret_cast<const __half2*>(&v[u]);
            #pragma unroll
            for (int j = 0; j < 4; j++) {
                float2 f = __half22float2(hp[j]);
                acc[2 * j]     += f.x;
                acc[2 * j + 1] += f.y;
            }
        }
    }
    for (; e < end; e++) {
        int s0 = g_col[e];
        uint4 v0 = Pv[(size_t)s0 * 8 + l];
        const __half2* h0 = reinterpret_cast<const __half2*>(&v0);
        #pragma unroll
        for (int j = 0; j < 4; j++) {
            float2 f0 = __half22float2(h0[j]);
            acc[2 * j]     += f0.x;
            acc[2 * j + 1] += f0.y;
        }
    }

    float4 b0 = reinterpret_cast<const float4*>(bias)[l * 2];
    float4 b1 = reinterpret_cast<const float4*>(bias)[l * 2 + 1];
    acc[0] = acc[0] * di + b0.x; acc[1] = acc[1] * di + b0.y;
    acc[2] = acc[2] * di + b0.z; acc[3] = acc[3] * di + b0.w;
    acc[4] = acc[4] * di + b1.x; acc[5] = acc[5] * di + b1.y;
    acc[6] = acc[6] * di + b1.z; acc[7] = acc[7] * di + b1.w;
    if (RELU) {
        #pragma unroll
        for (int j = 0; j < 8; j++) acc[j] = fmaxf(acc[j], 0.0f);
    }
    float4* Yo = reinterpret_cast<float4*>(Y + (size_t)node * 64 + l * 8);
    Yo[0] = make_float4(acc[0], acc[1], acc[2], acc[3]);
    Yo[1] = make_float4(acc[4], acc[5], acc[6], acc[7]);
}

// ---------------- launcher ----------------
extern "C" void kernel_launch(void* const* d_in, const int* in_sizes, int n_in,
                              void* d_out, int out_size) {
    const float* x  = (const float*)d_in[0];       // [n, 128]
    const int*   ei = (const int*)d_in[1];         // [2, E]
    const float* W1 = (const float*)d_in[2];       // [128, 64]
    const float* b1 = (const float*)d_in[3];       // [64]
    const float* W2 = (const float*)d_in[4];       // [64, 64]
    const float* b2 = (const float*)d_in[5];       // [64]
    float* out = (float*)d_out;                    // [n, 64]

    int n = in_sizes[0] / IN_CH;
    int E = in_sizes[1] / 2;
    const int* src = ei;
    const int* dst = ei + E;

    void* p;
    cudaGetSymbolAddress(&p, g_P);
    __half* P = (__half*)p;
    cudaGetSymbolAddress(&p, g_H);
    float* H = (float*)p;

    cudaFuncSetAttribute(gemm_tc_kernel<IN_CH, false>,
                         cudaFuncAttributeMaxDynamicSharedMemorySize, SMEM_GEMM_BYTES);
    cudaFuncSetAttribute(gemm_tc_kernel<HID, true>,
                         cudaFuncAttributeMaxDynamicSharedMemorySize, SMEM_GEMM_BYTES);

    int nb = (n + SCAN_B - 1) / SCAN_B;
    int eb2 = (E + 2 * 256 - 1) / (2 * 256);
    int spmm_blocks = (n * 8 + 255) / 256;
    int gemm_blocks = (n + 127) / 128;

    // Fork side stream: CSR build overlaps GEMM1. (Host objects leak by design;
    // destroying capture-participating streams/events mid-capture is illegal.)
    cudaStream_t s2;
    cudaStreamCreateWithFlags(&s2, cudaStreamNonBlocking);
    cudaEvent_t ev_fork, ev_scan, ev_join;
    cudaEventCreateWithFlags(&ev_fork, cudaEventDisableTiming);
    cudaEventCreateWithFlags(&ev_scan, cudaEventDisableTiming);
    cudaEventCreateWithFlags(&ev_join, cudaEventDisableTiming);

    cudaEventRecord(ev_fork, 0);
    cudaStreamWaitEvent(s2, ev_fork, 0);

    // side stream: count(+slot, resets ready) -> scan (re-zeroes deg) -> fill (no atomics)
    count_deg_kernel<<<eb2, 256, 0, s2>>>(dst, E);
    scan_fused_kernel<<<nb, SCAN_B, 0, s2>>>(n, E);
    cudaEventRecord(ev_scan, s2);
    fill_edges_kernel<<<eb2, 256, 0, s2>>>(src, dst, E);
    cudaEventRecord(ev_join, s2);

    // main stream: layer-1 projection (tensor cores), concurrent with CSR build
    gemm_tc_kernel<IN_CH, false><<<gemm_blocks, 256, SMEM_GEMM_BYTES>>>(x, W1, P, n);

    // scale P by dinv (needs scan only) — overlaps fill_edges
    cudaStreamWaitEvent(0, ev_scan, 0);
    scale_P_kernel<<<(n * 8 + 255) / 256, 256>>>(P, n);

    // aggregate layer 1 (needs fill)
    cudaStreamWaitEvent(0, ev_join, 0);
    spmm64_kernel<true><<<spmm_blocks, 256>>>(P, b1, H, n);

    // layer 2: project with dinv folded into epilogue, aggregate
    gemm_tc_kernel<HID, true><<<gemm_blocks, 256, SMEM_GEMM_BYTES>>>(H, W2, P, n);
    spmm64_kernel<false><<<spmm_blocks, 256>>>(P, b2, out, n);
}

// round 15
// speedup vs baseline: 1.3827x; 1.0009x over previous
#include <cuda_runtime.h>
#include <cuda_fp16.h>
#include <cstddef>
#include <cstdint>

#define N_NODES_MAX 50000
#define N_EDGES_MAX 800000
#define IN_CH 128
#define HID 64
#define SCAN_B 1024

// ---------------- device scratch (no allocation allowed) ----------------
__device__ int    g_deg[N_NODES_MAX];          // zero-init at load; re-zeroed by scan each run
__device__ int    g_row[N_NODES_MAX + 1];
__device__ float  g_dinv[N_NODES_MAX];
__device__ int    g_col[N_EDGES_MAX];          // src ids grouped by dst
__device__ int    g_slot[N_EDGES_MAX];         // per-edge rank within its dst bucket
__device__ int    g_bsum[(N_NODES_MAX + SCAN_B - 1) / SCAN_B + 1];
__device__ int    g_ready;                     // lookback counter
__device__ __half g_P[N_NODES_MAX * 64];       // fp16 projection buffer (layer 1)
__device__ __half g_P2[N_NODES_MAX * 64];      // fp16 pre-scaled layer-2 projection

// ---------------- cp.async helpers ----------------
__device__ __forceinline__ void cp_async16(uint32_t smem_addr, const void* gptr) {
    asm volatile("cp.async.cg.shared.global [%0], [%1], 16;\n"
                 :: "r"(smem_addr), "l"(gptr));
}
__device__ __forceinline__ void cp_commit() {
    asm volatile("cp.async.commit_group;\n");
}
template <int N>
__device__ __forceinline__ void cp_wait() {
    asm volatile("cp.async.wait_group %0;\n" :: "n"(N));
}

// ---------------- CSR build ----------------
// count: 2 edges/thread (max resident warps; ATOMG latency-bound), slot = atomic return
__global__ void count_deg_kernel(const int* __restrict__ dst, int n_edges) {
    if (blockIdx.x == 0 && threadIdx.x == 0) g_ready = 0;  // for scan (next launch)
    int i0 = (blockIdx.x * blockDim.x + threadIdx.x) * 2;
    if (i0 + 2 <= n_edges) {
        int2 d = *reinterpret_cast<const int2*>(dst + i0);
        int2 sl;
        sl.x = atomicAdd(&g_deg[d.x], 1);
        sl.y = atomicAdd(&g_deg[d.y], 1);
        *reinterpret_cast<int2*>(g_slot + i0) = sl;
    } else if (i0 < n_edges) {
        g_slot[i0] = atomicAdd(&g_deg[dst[i0]], 1);
    }
}

__device__ __forceinline__ int block_scan_incl(int v, int* warp_sums) {
    int lane = threadIdx.x & 31;
    int wid = threadIdx.x >> 5;
    int x = v;
    #pragma unroll
    for (int off = 1; off < 32; off <<= 1) {
        int y = __shfl_up_sync(0xFFFFFFFFu, x, off);
        if (lane >= off) x += y;
    }
    if (lane == 31) warp_sums[wid] = x;
    __syncthreads();
    if (wid == 0) {
        int w = warp_sums[lane];
        #pragma unroll
        for (int off = 1; off < 32; off <<= 1) {
            int y = __shfl_up_sync(0xFFFFFFFFu, w, off);
            if (lane >= off) w += y;
        }
        warp_sums[lane] = w;
    }
    __syncthreads();
    return x + ((wid > 0) ? warp_sums[wid - 1] : 0);
}

// Single-pass scan with grid-resident counter wait (49 blocks << 148 SMs).
// Also RE-ZEROES g_deg so the next kernel_launch starts clean (replaces memset).
__global__ void __launch_bounds__(SCAN_B) scan_fused_kernel(int n, int E) {
    __shared__ int warp_sums[32];
    __shared__ int s_off;
    int b = blockIdx.x;
    int i = b * SCAN_B + threadIdx.x;
    int v = (i < n) ? g_deg[i] : 0;
    int incl = block_scan_incl(v, warp_sums);

    if (threadIdx.x == 0) {
        g_bsum[b] = warp_sums[31];
        __threadfence();
        atomicAdd(&g_ready, 1);
        while (atomicAdd(&g_ready, 0) < (int)gridDim.x) {}
        __threadfence();
        int s = 0;
        for (int j = 0; j < b; j++) s += g_bsum[j];
        s_off = s;
    }
    __syncthreads();

    if (i < n) {
        g_row[i] = incl - v + s_off;
        g_dinv[i] = rsqrtf((float)v + 1.0f);  // deg incl. self-loop
        g_deg[i] = 0;                          // ready for next launch
    }
    if (b == 0 && threadIdx.x == 0) g_row[n] = E;
}

// fill: NO atomics — p = row[dst] + slot[i]; 2 edges/thread
__global__ void fill_edges_kernel(const int* __restrict__ src,
                                  const int* __restrict__ dst, int n_edges) {
    int i0 = (blockIdx.x * blockDim.x + threadIdx.x) * 2;
    if (i0 + 2 <= n_edges) {
        int2 d = *reinterpret_cast<const int2*>(dst + i0);
        int2 s = *reinterpret_cast<const int2*>(src + i0);
        int2 sl = *reinterpret_cast<const int2*>(g_slot + i0);
        g_col[g_row[d.x] + sl.x] = s.x;
        g_col[g_row[d.y] + sl.y] = s.y;
    } else if (i0 < n_edges) {
        g_col[g_row[dst[i0]] + g_slot[i0]] = src[i0];
    }
}

// scale P rows by dinv: P'[i] = dinv[i] * P[i]
__global__ void scale_P_kernel(__half* __restrict__ P, int n) {
    int t = blockIdx.x * blockDim.x + threadIdx.x;
    int node = t >> 3;
    if (node >= n) return;
    int l = t & 7;
    float di = g_dinv[node];
    uint4 v = reinterpret_cast<uint4*>(P)[(size_t)node * 8 + l];
    __half2* hp = reinterpret_cast<__half2*>(&v);
    #pragma unroll
    for (int j = 0; j < 4; j++) {
        float2 f = __half22float2(hp[j]);
        hp[j] = __floats2half2_rn(f.x * di, f.y * di);
    }
    reinterpret_cast<uint4*>(P)[(size_t)node * 8 + l] = v;
}

// ---------------- MMA helpers ----------------
__device__ __forceinline__ unsigned cvt_tf32(unsigned bits) {
    unsigned r;
    asm("cvt.rna.tf32.f32 %0, %1;" : "=r"(r) : "f"(__uint_as_float(bits)));
    return r;
}

__device__ __forceinline__ void mma_tf32(float* c, unsigned a0, unsigned a1,
                                         unsigned a2, unsigned a3,
                                         unsigned b0, unsigned b1) {
    asm volatile(
        "mma.sync.aligned.m16n8k8.row.col.f32.tf32.tf32.f32 "
        "{%0,%1,%2,%3}, {%4,%5,%6,%7}, {%8,%9}, {%0,%1,%2,%3};"
        : "+f"(c[0]), "+f"(c[1]), "+f"(c[2]), "+f"(c[3])
        : "r"(a0), "r"(a1), "r"(a2), "r"(a3), "r"(b0), "r"(b1));
}

__device__ __forceinline__ void mma_f16(float* c, unsigned a0, unsigned a1,
                                        unsigned a2, unsigned a3,
                                        unsigned b0, unsigned b1) {
    asm volatile(
        "mma.sync.aligned.m16n8k16.row.col.f32.f16.f16.f32 "
        "{%0,%1,%2,%3}, {%4,%5,%6,%7}, {%8,%9}, {%0,%1,%2,%3};"
        : "+f"(c[0]), "+f"(c[1]), "+f"(c[2]), "+f"(c[3])
        : "r"(a0), "r"(a1), "r"(a2), "r"(a3), "r"(b0), "r"(b1));
}

// Dynamic smem layout: Xs[2][128][40] then Ws[2][32][72]  (59392 B total)
#define XS_STRIDE 40
#define WS_STRIDE 72
#define XS_WORDS (2 * 128 * XS_STRIDE)
#define SMEM_GEMM_BYTES ((XS_WORDS + 2 * 32 * WS_STRIDE) * 4)

// ---------------- layer-1 GEMM: 128x64 tile, tf32, cp.async 2-stage ----------------
template <int K>
__global__ void __launch_bounds__(256) gemm_tc_kernel(const float* __restrict__ X,
                                                      const float* __restrict__ W,
                                                      __half* __restrict__ Y, int n) {
    const int KC = 32;
    const int NC = K / KC;
    extern __shared__ unsigned smem_dyn[];
    unsigned* Xs = smem_dyn;                 // Xs[st][row][k]
    unsigned* Ws = smem_dyn + XS_WORDS;      // Ws[st][k][nn]

    int t = threadIdx.x;
    int lane = t & 31;
    int warp = t >> 5;          // 0..7
    int row0 = blockIdx.x * 128;
    int m_w = warp * 16;
    int g = lane >> 2;          // 0..7
    int tig = lane & 3;         // 0..3

    int xr[4], xq[4];
    const float* xsrc[4];
    #pragma unroll
    for (int u = 0; u < 4; u++) {
        int idx = t + u * 256;
        xr[u] = idx >> 3;        // 0..127
        xq[u] = idx & 7;         // float4 along k
        int row = row0 + xr[u];
        if (row >= n) row = n - 1;
        xsrc[u] = X + (size_t)row * K + xq[u] * 4;
    }
    int wk[2], wq[2];
    #pragma unroll
    for (int u = 0; u < 2; u++) {
        int idx = t + u * 256;
        wk[u] = idx >> 4;        // 0..31
        wq[u] = idx & 15;        // float4 along n
    }

    auto load_chunk = [&](int st, int kc) {
        #pragma unroll
        for (int u = 0; u < 4; u++)
            cp_async16((uint32_t)__cvta_generic_to_shared(
                           &Xs[st * 128 * XS_STRIDE + xr[u] * XS_STRIDE + xq[u] * 4]),
                       xsrc[u] + kc);
        #pragma unroll
        for (int u = 0; u < 2; u++)
            cp_async16((uint32_t)__cvta_generic_to_shared(
                           &Ws[st * 32 * WS_STRIDE + wk[u] * WS_STRIDE + wq[u] * 4]),
                       W + (size_t)(kc + wk[u]) * 64 + wq[u] * 4);
        cp_commit();
    };

    float c[8][4];
    #pragma unroll
    for (int j = 0; j < 8; j++)
        #pragma unroll
        for (int q = 0; q < 4; q++) c[j][q] = 0.0f;

    load_chunk(0, 0);

    #pragma unroll
    for (int cidx = 0; cidx < NC; cidx++) {
        int buf = cidx & 1;
        if (cidx + 1 < NC) {
            load_chunk(buf ^ 1, (cidx + 1) * KC);
            cp_wait<1>();
        } else {
            cp_wait<0>();
        }
        __syncthreads();

        const unsigned* Xb = Xs + buf * 128 * XS_STRIDE;
        const unsigned* Wb = Ws + buf * 32 * WS_STRIDE;
        #pragma unroll
        for (int s = 0; s < KC / 8; s++) {
            int k0 = s * 8;
            unsigned a0 = cvt_tf32(Xb[(m_w + g) * XS_STRIDE + k0 + tig]);
            unsigned a1 = cvt_tf32(Xb[(m_w + g + 8) * XS_STRIDE + k0 + tig]);
            unsigned a2 = cvt_tf32(Xb[(m_w + g) * XS_STRIDE + k0 + tig + 4]);
            unsigned a3 = cvt_tf32(Xb[(m_w + g + 8) * XS_STRIDE + k0 + tig + 4]);
            #pragma unroll
            for (int j = 0; j < 8; j++) {
                unsigned b0 = cvt_tf32(Wb[(k0 + tig) * WS_STRIDE + j * 8 + g]);
                unsigned b1 = cvt_tf32(Wb[(k0 + tig + 4) * WS_STRIDE + j * 8 + g]);
                mma_tf32(c[j], a0, a1, a2, a3, b0, b1);
            }
        }
        __syncthreads();
    }

    int r0 = row0 + m_w + g;
    int r1 = r0 + 8;
    #pragma unroll
    for (int j = 0; j < 8; j++) {
        int colb = j * 8 + 2 * tig;
        if (r0 < n)
            *reinterpret_cast<__half2*>(Y + (size_t)r0 * 64 + colb) =
                __floats2half2_rn(c[j][0], c[j][1]);
        if (r1 < n)
            *reinterpret_cast<__half2*>(Y + (size_t)r1 * 64 + colb) =
                __floats2half2_rn(c[j][2], c[j][3]);
    }
}

// ---------------- FUSED: spmm layer-1 (+b1, relu) -> h in smem -> h @ W2 (fp16 MMA) ----------------
// Block = 128 nodes, 256 threads. Eliminates the fp32 H buffer and the gemm2 launch.
// Output: P2'[r] = dinv[r] * (h @ W2)[r]  (fp16, pre-scaled for spmm2).
__global__ void __launch_bounds__(256) spmm_gemm_fused_kernel(
    const __half* __restrict__ P, const float* __restrict__ bias1,
    const float* __restrict__ W2, __half* __restrict__ P2, int n)
{
    __shared__ __half hs[128][72];    // h tile, stride 72 halves (conflict-free frags)
    __shared__ __half w2t[64][72];    // W2 transposed: w2t[n][k]

    int t = threadIdx.x;
    int row0 = blockIdx.x * 128;

    // load W2 [64][64] fp32 row-major -> w2t[n][k] fp16 (coalesced read)
    #pragma unroll
    for (int i = 0; i < 16; i++) {
        int idx = t + i * 256;
        int k = idx >> 6;
        int nn = idx & 63;
        w2t[nn][k] = __float2half(W2[idx]);
    }

    // ---- spmm phase: 8 lanes/node, 32 nodes/pass, 4 passes ----
    const uint4* Pv = reinterpret_cast<const uint4*>(P);
    int l = t & 7;
    float4 bb0 = reinterpret_cast<const float4*>(bias1)[l * 2];
    float4 bb1 = reinterpret_cast<const float4*>(bias1)[l * 2 + 1];

    #pragma unroll
    for (int p = 0; p < 4; p++) {
        int nl = p * 32 + (t >> 3);
        int node = row0 + nl;
        uint4 store = make_uint4(0, 0, 0, 0);
        if (node < n) {
            float di = g_dinv[node];
            float acc[8];
            {
                uint4 v = Pv[(size_t)node * 8 + l];   // self-loop term P'[node]
                const __half2* hp = reinterpret_cast<const __half2*>(&v);
                #pragma unroll
                for (int j = 0; j < 4; j++) {
                    float2 f = __half22float2(hp[j]);
                    acc[2 * j]     = f.x;
                    acc[2 * j + 1] = f.y;
                }
            }
            int e = g_row[node];
            int end = g_row[node + 1];
            for (; e + 8 <= end; e += 8) {
                int sidx[8];
                #pragma unroll
                for (int u = 0; u < 8; u++) sidx[u] = g_col[e + u];
                uint4 v[8];
                #pragma unroll
                for (int u = 0; u < 8; u++) v[u] = Pv[(size_t)sidx[u] * 8 + l];
                #pragma unroll
                for (int u = 0; u < 8; u++) {
                    const __half2* hp = reinterpret_cast<const __half2*>(&v[u]);
                    #pragma unroll
                    for (int j = 0; j < 4; j++) {
                        float2 f = __half22float2(hp[j]);
                        acc[2 * j]     += f.x;
                        acc[2 * j + 1] += f.y;
                    }
                }
            }
            for (; e < end; e++) {
                int s0 = g_col[e];
                uint4 v0 = Pv[(size_t)s0 * 8 + l];
                const __half2* h0 = reinterpret_cast<const __half2*>(&v0);
                #pragma unroll
                for (int j = 0; j < 4; j++) {
                    float2 f0 = __half22float2(h0[j]);
                    acc[2 * j]     += f0.x;
                    acc[2 * j + 1] += f0.y;
                }
            }
            // h = relu(di*acc + b1), packed fp16
            float h0 = fmaxf(acc[0] * di + bb0.x, 0.0f);
            float h1 = fmaxf(acc[1] * di + bb0.y, 0.0f);
            float h2 = fmaxf(acc[2] * di + bb0.z, 0.0f);
            float h3 = fmaxf(acc[3] * di + bb0.w, 0.0f);
            float h4 = fmaxf(acc[4] * di + bb1.x, 0.0f);
            float h5 = fmaxf(acc[5] * di + bb1.y, 0.0f);
            float h6 = fmaxf(acc[6] * di + bb1.z, 0.0f);
            float h7 = fmaxf(acc[7] * di + bb1.w, 0.0f);
            __half2 hh[4];
            hh[0] = __floats2half2_rn(h0, h1);
            hh[1] = __floats2half2_rn(h2, h3);
            hh[2] = __floats2half2_rn(h4, h5);
            hh[3] = __floats2half2_rn(h6, h7);
            store = *reinterpret_cast<const uint4*>(hh);
        }
        *reinterpret_cast<uint4*>(&hs[nl][l * 8]) = store;  // 16B aligned (144*nl + 16*l)
    }
    __syncthreads();

    // ---- MMA phase: fp16 m16n8k16, warp w -> rows [w*16, w*16+16), all 64 cols ----
    int lane = t & 31;
    int warp = t >> 5;
    int m_w = warp * 16;
    int g = lane >> 2;
    int tig = lane & 3;

    float c[8][4];
    #pragma unroll
    for (int j = 0; j < 8; j++)
        #pragma unroll
        for (int q = 0; q < 4; q++) c[j][q] = 0.0f;

    #pragma unroll
    for (int kb = 0; kb < 64; kb += 16) {
        unsigned a0 = *reinterpret_cast<const unsigned*>(&hs[m_w + g][kb + 2 * tig]);
        unsigned a1 = *reinterpret_cast<const unsigned*>(&hs[m_w + g + 8][kb + 2 * tig]);
        unsigned a2 = *reinterpret_cast<const unsigned*>(&hs[m_w + g][kb + 8 + 2 * tig]);
        unsigned a3 = *reinterpret_cast<const unsigned*>(&hs[m_w + g + 8][kb + 8 + 2 * tig]);
        #pragma unroll
        for (int j = 0; j < 8; j++) {
            unsigned b0 = *reinterpret_cast<const unsigned*>(&w2t[j * 8 + g][kb + 2 * tig]);
            unsigned b1 = *reinterpret_cast<const unsigned*>(&w2t[j * 8 + g][kb + 8 + 2 * tig]);
            mma_f16(c[j], a0, a1, a2, a3, b0, b1);
        }
    }

    // epilogue: P2'[r] = dinv[r] * c
    int r0 = row0 + m_w + g;
    int r1 = r0 + 8;
    float s0 = (r0 < n) ? g_dinv[r0] : 0.0f;
    float s1 = (r1 < n) ? g_dinv[r1] : 0.0f;
    #pragma unroll
    for (int j = 0; j < 8; j++) {
        int colb = j * 8 + 2 * tig;
        if (r0 < n)
            *reinterpret_cast<__half2*>(P2 + (size_t)r0 * 64 + colb) =
                __floats2half2_rn(c[j][0] * s0, c[j][1] * s0);
        if (r1 < n)
            *reinterpret_cast<__half2*>(P2 + (size_t)r1 * 64 + colb) =
                __floats2half2_rn(c[j][2] * s1, c[j][3] * s1);
    }
}

// ---------------- layer-2 aggregation: out = dinv[d]*(ΣP2'[src] + P2'[d]) + b2 ----------------
__global__ void __launch_bounds__(256) spmm64_kernel(const __half* __restrict__ P,
                                                     const float* __restrict__ bias,
                                                     float* __restrict__ Y, int n) {
    int t = blockIdx.x * blockDim.x + threadIdx.x;
    int node = t >> 3;
    if (node >= n) return;
    int l = t & 7;

    const uint4* Pv = reinterpret_cast<const uint4*>(P);
    float di = g_dinv[node];

    float acc[8];
    {
        uint4 v = Pv[(size_t)node * 8 + l];
        const __half2* hp = reinterpret_cast<const __half2*>(&v);
        #pragma unroll
        for (int j = 0; j < 4; j++) {
            float2 f = __half22float2(hp[j]);
            acc[2 * j]     = f.x;
            acc[2 * j + 1] = f.y;
        }
    }

    int e = g_row[node];
    int end = g_row[node + 1];
    for (; e + 8 <= end; e += 8) {
        int sidx[8];
        #pragma unroll
        for (int u = 0; u < 8; u++) sidx[u] = g_col[e + u];
        uint4 v[8];
        #pragma unroll
        for (int u = 0; u < 8; u++) v[u] = Pv[(size_t)sidx[u] * 8 + l];
        #pragma unroll
        for (int u = 0; u < 8; u++) {
            const __half2* hp = reinterpret_cast<const __half2*>(&v[u]);
            #pragma unroll
            for (int j = 0; j < 4; j++) {
                float2 f = __half22float2(hp[j]);
                acc[2 * j]     += f.x;
                acc[2 * j + 1] += f.y;
            }
        }
    }
    for (; e < end; e++) {
        int s0 = g_col[e];
        uint4 v0 = Pv[(size_t)s0 * 8 + l];
        const __half2* h0 = reinterpret_cast<const __half2*>(&v0);
        #pragma unroll
        for (int j = 0; j < 4; j++) {
            float2 f0 = __half22float2(h0[j]);
            acc[2 * j]     += f0.x;
            acc[2 * j + 1] += f0.y;
        }
    }

    float4 b0 = reinterpret_cast<const float4*>(bias)[l * 2];
    float4 b1 = reinterpret_cast<const float4*>(bias)[l * 2 + 1];
    acc[0] = acc[0] * di + b0.x; acc[1] = acc[1] * di + b0.y;
    acc[2] = acc[2] * di + b0.z; acc[3] = acc[3] * di + b0.w;
    acc[4] = acc[4] * di + b1.x; acc[5] = acc[5] * di + b1.y;
    acc[6] = acc[6] * di + b1.z; acc[7] = acc[7] * di + b1.w;
    float4* Yo = reinterpret_cast<float4*>(Y + (size_t)node * 64 + l * 8);
    Yo[0] = make_float4(acc[0], acc[1], acc[2], acc[3]);
    Yo[1] = make_float4(acc[4], acc[5], acc[6], acc[7]);
}

// ---------------- launcher ----------------
extern "C" void kernel_launch(void* const* d_in, const int* in_sizes, int n_in,
                              void* d_out, int out_size) {
    const float* x  = (const float*)d_in[0];       // [n, 128]
    const int*   ei = (const int*)d_in[1];         // [2, E]
    const float* W1 = (const float*)d_in[2];       // [128, 64]
    const float* b1 = (const float*)d_in[3];       // [64]
    const float* W2 = (const float*)d_in[4];       // [64, 64]
    const float* b2 = (const float*)d_in[5];       // [64]
    float* out = (float*)d_out;                    // [n, 64]

    int n = in_sizes[0] / IN_CH;
    int E = in_sizes[1] / 2;
    const int* src = ei;
    const int* dst = ei + E;

    void* p;
    cudaGetSymbolAddress(&p, g_P);
    __half* P = (__half*)p;
    cudaGetSymbolAddress(&p, g_P2);
    __half* P2 = (__half*)p;

    cudaFuncSetAttribute(gemm_tc_kernel<IN_CH>,
                         cudaFuncAttributeMaxDynamicSharedMemorySize, SMEM_GEMM_BYTES);

    int nb = (n + SCAN_B - 1) / SCAN_B;
    int eb2 = (E + 2 * 256 - 1) / (2 * 256);
    int spmm_blocks = (n * 8 + 255) / 256;
    int gemm_blocks = (n + 127) / 128;

    // Fork side stream: CSR build overlaps GEMM1. (Host objects leak by design;
    // destroying capture-participating streams/events mid-capture is illegal.)
    cudaStream_t s2;
    cudaStreamCreateWithFlags(&s2, cudaStreamNonBlocking);
    cudaEvent_t ev_fork, ev_scan, ev_join;
    cudaEventCreateWithFlags(&ev_fork, cudaEventDisableTiming);
    cudaEventCreateWithFlags(&ev_scan, cudaEventDisableTiming);
    cudaEventCreateWithFlags(&ev_join, cudaEventDisableTiming);

    cudaEventRecord(ev_fork, 0);
    cudaStreamWaitEvent(s2, ev_fork, 0);

    // side stream: count(+slot, resets ready) -> scan (re-zeroes deg) -> fill (no atomics)
    count_deg_kernel<<<eb2, 256, 0, s2>>>(dst, E);
    scan_fused_kernel<<<nb, SCAN_B, 0, s2>>>(n, E);
    cudaEventRecord(ev_scan, s2);
    fill_edges_kernel<<<eb2, 256, 0, s2>>>(src, dst, E);
    cudaEventRecord(ev_join, s2);

    // main stream: layer-1 projection (tensor cores), concurrent with CSR build
    gemm_tc_kernel<IN_CH><<<gemm_blocks, 256, SMEM_GEMM_BYTES>>>(x, W1, P, n);

    // scale P by dinv (needs scan only) — overlaps fill_edges
    cudaStreamWaitEvent(0, ev_scan, 0);
    scale_P_kernel<<<(n * 8 + 255) / 256, 256>>>(P, n);

    // fused: spmm layer1 (+b1, relu) -> h @ W2 -> pre-scaled P2' (needs fill)
    cudaStreamWaitEvent(0, ev_join, 0);
    spmm_gemm_fused_kernel<<<gemm_blocks, 256>>>(P, b1, W2, P2, n);

    // layer-2 aggregation (+b2) -> out
    spmm64_kernel<<<spmm_blocks, 256>>>(P2, b2, out, n);
}